// round 2
// baseline (speedup 1.0000x reference)
#include <cuda_runtime.h>
#include <math.h>

#define H 96
#define W 96
#define C 128
#define OCH 128
#define BATCH 2
#define HP 98
#define WP 98
#define NPIX (BATCH*H*W)   // 18432
#define PT 32              // pixel tile for main GEMM

// ---------------- scratch (device globals; no allocation allowed) ----------
__device__ float  g_xp[BATCH*HP*WP*C];     // padded NHWC input, ~9.8MB (borders stay 0)
__device__ float  g_wg[9*C*OCH];           // main conv weights [n][c][o]
__device__ float  g_wmeta[9*21*C];         // meta conv weights [n][f][c]
__device__ float4 g_mg[NPIX*9];            // bilinear weights (lt, rb, lb, rt)
__device__ int4   g_midx[NPIX*9];          // flat gather indices into xp (pixel units)

// ---------------- weight prep ----------------------------------------------
__global__ void prep_weights(const float* __restrict__ conv_w,
                             const float* __restrict__ pconv_w,
                             const float* __restrict__ adconv_w) {
    int lin = blockIdx.x * blockDim.x + threadIdx.x;
    if (lin < 9*C*OCH) {
        int o = lin % OCH;
        int c = (lin / OCH) % C;
        int n = lin / (OCH*C);
        g_wg[lin] = conv_w[(o*C + c)*9 + n];
    }
    if (lin < 9*21*C) {
        int c = lin % C;
        int f = (lin / C) % 21;
        int n = lin / (21*C);
        g_wmeta[lin] = (f < 18) ? pconv_w[(f*C + c)*9 + n]
                                : adconv_w[((f-18)*C + c)*9 + n];
    }
}

// ---------------- NCHW -> padded NHWC transpose -----------------------------
__global__ void transpose_pad(const float* __restrict__ x) {
    __shared__ float tile[32][33];
    int b = blockIdx.z, i = blockIdx.y;
    int tj = blockIdx.x % 3;        // j tile (96/32)
    int tc = blockIdx.x / 3;        // c tile (128/32)
    int j0 = tj * 32, c0 = tc * 32;
    int tx = threadIdx.x, ty = threadIdx.y;   // 32 x 8

    const float* src = x + ((size_t)(b*C) * H + i) * W;
    #pragma unroll
    for (int q = 0; q < 4; q++) {
        int c = c0 + ty + q*8;
        tile[ty + q*8][tx] = src[(size_t)c * H * W + j0 + tx];
    }
    __syncthreads();
    float* dst = g_xp + (((size_t)b*HP) + (i+1)) * WP * C;
    #pragma unroll
    for (int q = 0; q < 4; q++) {
        int jj = j0 + ty + q*8;
        dst[(size_t)(jj+1)*C + c0 + tx] = tile[tx][ty + q*8];
    }
}

// ---------------- meta: offset conv + sigmoid + bilinear setup --------------
// one warp per output pixel
__global__ void meta_kernel(const float* __restrict__ pconv_b,
                            const float* __restrict__ adconv_b) {
    int gwarp = (blockIdx.x * blockDim.x + threadIdx.x) >> 5;
    int lane  = threadIdx.x & 31;
    if (gwarp >= NPIX) return;
    int pix = gwarp;
    int b = pix / (H*W);
    int rem = pix % (H*W);
    int i = rem / W;
    int j = rem % W;

    float part[21];
    #pragma unroll
    for (int f = 0; f < 21; f++) part[f] = 0.f;

    const float4* wm4 = (const float4*)g_wmeta;
    #pragma unroll
    for (int n = 0; n < 9; n++) {
        int kr = n / 3, kc = n % 3;
        const float4* xr = (const float4*)(g_xp + (size_t)(((b*HP) + (i+kr))*WP + (j+kc)) * C);
        float4 xv = xr[lane];
        const float4* wrow = wm4 + (size_t)(n*21)*32 + lane;
        #pragma unroll
        for (int f = 0; f < 21; f++) {
            float4 wv = wrow[(size_t)f*32];
            part[f] += xv.x*wv.x + xv.y*wv.y + xv.z*wv.z + xv.w*wv.w;
        }
    }
    #pragma unroll
    for (int f = 0; f < 21; f++) {
        #pragma unroll
        for (int s = 16; s; s >>= 1)
            part[f] += __shfl_xor_sync(0xffffffffu, part[f], s);
    }

    if (lane < 9) {
        int n = lane;
        float offx = part[n]     + pconv_b[n];
        float offy = part[9 + n] + pconv_b[9 + n];
        int m = n % 3;
        float adv = part[18 + m] + adconv_b[m];
        float adb = 1.f - 1.f / (1.f + expf(-adv));   // 1 - sigmoid
        float pnx = (float)(n / 3 - 1);
        float pny = (float)(n % 3 - 1);
        float px = (float)(i + 1) + pnx * (1.f + 2.f*adb) + offx;
        float py = (float)(j + 1) + pny * (1.f + 2.f*adb) + offy;

        float flx = floorf(px), fly = floorf(py);
        int qltx = min(max((int)flx,     0), HP-1);
        int qlty = min(max((int)fly,     0), WP-1);
        int qrbx = min(max((int)flx + 1, 0), HP-1);
        int qrby = min(max((int)fly + 1, 0), WP-1);
        bool mx = (px < 1.f) || (px > (float)(HP-2));
        bool my = (py < 1.f) || (py > (float)(WP-2));
        float pxe = mx ? fminf(fmaxf(flx, 0.f), (float)(HP-1)) : fminf(fmaxf(px, 0.f), (float)(HP-1));
        float pye = my ? fminf(fmaxf(fly, 0.f), (float)(WP-1)) : fminf(fmaxf(py, 0.f), (float)(WP-1));

        float glt_x = 1.f + ((float)qltx - pxe);
        float glt_y = 1.f + ((float)qlty - pye);
        float grb_x = 1.f - ((float)qrbx - pxe);
        float grb_y = 1.f - ((float)qrby - pye);

        float4 g = make_float4(glt_x*glt_y, grb_x*grb_y, glt_x*grb_y, grb_x*glt_y);
        int base = b * HP * WP;
        int4 idx = make_int4(base + qltx*WP + qlty,
                             base + qrbx*WP + qrby,
                             base + qltx*WP + qrby,
                             base + qrbx*WP + qlty);
        g_mg[pix*9 + n]   = g;
        g_midx[pix*9 + n] = idx;
    }
}

// ---------------- main gather-GEMM ------------------------------------------
// out[o, p] = sum_n sum_c wg[n][c][o] * xoff[n][c][p]
// block: 256 threads; 128 o x 32 p tile; thread tile 4x4
__global__ void __launch_bounds__(256) main_kernel(float* __restrict__ out) {
    __shared__ float  xs[C][PT + 1];      // gathered x_off for current n: [c][p]
    __shared__ float4 ws4[32 * 32];       // weights chunk: [32 c][128 o] as float4
    __shared__ float4 sg[PT];
    __shared__ int4   sidx[PT];

    int tid = threadIdx.x;
    int tx = tid & 7;    // pixel group: p = tx*4 .. tx*4+3
    int ty = tid >> 3;   // o group:     o = ty*4 .. ty*4+3
    int pt0 = blockIdx.x * PT;
    int pbase = tx * 4;

    float acc[4][4];
    #pragma unroll
    for (int a = 0; a < 4; a++)
        #pragma unroll
        for (int bq = 0; bq < 4; bq++) acc[a][bq] = 0.f;

    const float4* xp4 = (const float4*)g_xp;

    for (int n = 0; n < 9; n++) {
        __syncthreads();   // previous iteration done reading xs / sg
        if (tid < PT) {
            sg[tid]   = g_mg[(size_t)(pt0 + tid)*9 + n];
            sidx[tid] = g_midx[(size_t)(pt0 + tid)*9 + n];
        }
        __syncthreads();

        // gather x_off[n] for this pixel tile: 8 threads/pixel, 16 channels each
        {
            int pl = tid >> 3;      // pixel 0..31
            int cg = tid & 7;       // channel group 0..7
            float4 g = sg[pl];
            int4  id = sidx[pl];
            const float4* plt = xp4 + (size_t)id.x * 32;
            const float4* prb = xp4 + (size_t)id.y * 32;
            const float4* plb = xp4 + (size_t)id.z * 32;
            const float4* prt = xp4 + (size_t)id.w * 32;
            #pragma unroll
            for (int q = 0; q < 4; q++) {
                int c4 = cg*4 + q;
                float4 a = plt[c4], r = prb[c4], lb = plb[c4], rt = prt[c4];
                float4 v;
                v.x = g.x*a.x + g.y*r.x + g.z*lb.x + g.w*rt.x;
                v.y = g.x*a.y + g.y*r.y + g.z*lb.y + g.w*rt.y;
                v.z = g.x*a.z + g.y*r.z + g.z*lb.z + g.w*rt.z;
                v.w = g.x*a.w + g.y*r.w + g.z*lb.w + g.w*rt.w;
                int c = c4*4;
                xs[c+0][pl] = v.x;
                xs[c+1][pl] = v.y;
                xs[c+2][pl] = v.z;
                xs[c+3][pl] = v.w;
            }
        }

        // K chunks of 32 channels
        for (int kc = 0; kc < 4; kc++) {
            __syncthreads();   // gather done / previous ws consumers done
            const float4* wgc = (const float4*)g_wg + ((size_t)n*C + kc*32) * 32;
            ws4[tid]       = wgc[tid];
            ws4[tid + 256] = wgc[tid + 256];
            ws4[tid + 512] = wgc[tid + 512];
            ws4[tid + 768] = wgc[tid + 768];
            __syncthreads();

            #pragma unroll
            for (int k = 0; k < 32; k++) {
                float4 wf = ws4[k*32 + ty];
                int ck = kc*32 + k;
                float x0 = xs[ck][pbase + 0];
                float x1 = xs[ck][pbase + 1];
                float x2 = xs[ck][pbase + 2];
                float x3 = xs[ck][pbase + 3];
                acc[0][0] += wf.x*x0; acc[0][1] += wf.x*x1; acc[0][2] += wf.x*x2; acc[0][3] += wf.x*x3;
                acc[1][0] += wf.y*x0; acc[1][1] += wf.y*x1; acc[1][2] += wf.y*x2; acc[1][3] += wf.y*x3;
                acc[2][0] += wf.z*x0; acc[2][1] += wf.z*x1; acc[2][2] += wf.z*x2; acc[2][3] += wf.z*x3;
                acc[3][0] += wf.w*x0; acc[3][1] += wf.w*x1; acc[3][2] += wf.w*x2; acc[3][3] += wf.w*x3;
            }
        }
    }

    // write: pixel tile is 32 consecutive linear pixels (same b, same row i)
    int b = pt0 / (H*W);
    int rem = pt0 % (H*W);
    int i = rem / W;
    int j0 = rem % W;
    #pragma unroll
    for (int uo = 0; uo < 4; uo++) {
        int o = ty*4 + uo;
        float* orow = out + (((size_t)b*OCH + o)*H + i)*W + j0;
        #pragma unroll
        for (int up = 0; up < 4; up++) {
            orow[pbase + up] = acc[uo][up];
        }
    }
}

// ---------------- launcher ---------------------------------------------------
extern "C" void kernel_launch(void* const* d_in, const int* in_sizes, int n_in,
                              void* d_out, int out_size) {
    const float* x        = (const float*)d_in[0];
    const float* conv_w   = (const float*)d_in[1];
    const float* pconv_w  = (const float*)d_in[2];
    const float* pconv_b  = (const float*)d_in[3];
    const float* adconv_w = (const float*)d_in[4];
    const float* adconv_b = (const float*)d_in[5];
    float* out = (float*)d_out;

    prep_weights<<<576, 256>>>(conv_w, pconv_w, adconv_w);
    transpose_pad<<<dim3(12, 96, 2), dim3(32, 8)>>>(x);
    meta_kernel<<<NPIX/8, 256>>>(pconv_b, adconv_b);
    main_kernel<<<NPIX/PT, 256>>>(out);
}

// round 3
// speedup vs baseline: 1.1781x; 1.1781x over previous
#include <cuda_runtime.h>
#include <math.h>

#define H 96
#define W 96
#define C 128
#define OCH 128
#define BATCH 2
#define HP 98
#define WP 98
#define NPIX (BATCH*H*W)   // 18432
#define PT 32              // pixel tile for main GEMM

// xsd row layout: 8 chunks of 32B (4 pixels as dup-pairs), chunks 4..7 shifted +16B
// row stride = 272 bytes (68 floats). POSB(p) = (p>>2)*32 + (p>>4)*16 + (p&3)*8
#define XSD_ROW 272

// dynamic smem layout (bytes)
#define SG_OFF    0
#define SIDX_OFF  512
#define WS_OFF    1024
#define XSD_OFF   (1024 + 65536)
#define SMEM_BYTES (XSD_OFF + C*XSD_ROW)   // 1024 + 65536 + 34816 = 101376

// ---------------- scratch (device globals; no allocation allowed) ----------
__device__ float  g_xp[BATCH*HP*WP*C];     // padded NHWC input (~9.8MB, borders 0)
__device__ float  g_wg[9*C*OCH];           // main conv weights [n][c][o]
__device__ float  g_wmeta[9*21*C];         // meta conv weights [n][f][c]
__device__ float4 g_mg[NPIX*9];            // bilinear weights (lt, rb, lb, rt)
__device__ int4   g_midx[NPIX*9];          // flat gather indices into xp (pixel units)

// f32x2 packed FMA: d = a*b + d (two independent fp32 lanes in one 64-bit reg)
#define FMA2(d, a, b) asm("fma.rn.f32x2 %0, %1, %2, %0;" : "+l"(d) : "l"(a), "l"(b))

static __device__ __forceinline__ unsigned long long dup2(float v) {
    unsigned long long r;
    asm("mov.b64 %0, {%1, %1};" : "=l"(r) : "f"(v));
    return r;
}
static __device__ __forceinline__ float u64lo(unsigned long long u) {
    return __uint_as_float((unsigned)(u & 0xffffffffu));
}
static __device__ __forceinline__ float u64hi(unsigned long long u) {
    return __uint_as_float((unsigned)(u >> 32));
}

// ---------------- weight prep ----------------------------------------------
__global__ void prep_weights(const float* __restrict__ conv_w,
                             const float* __restrict__ pconv_w,
                             const float* __restrict__ adconv_w) {
    int lin = blockIdx.x * blockDim.x + threadIdx.x;
    if (lin < 9*C*OCH) {
        int o = lin % OCH;
        int c = (lin / OCH) % C;
        int n = lin / (OCH*C);
        g_wg[lin] = conv_w[(o*C + c)*9 + n];
    }
    if (lin < 9*21*C) {
        int c = lin % C;
        int f = (lin / C) % 21;
        int n = lin / (21*C);
        g_wmeta[lin] = (f < 18) ? pconv_w[(f*C + c)*9 + n]
                                : adconv_w[((f-18)*C + c)*9 + n];
    }
}

// ---------------- NCHW -> padded NHWC transpose -----------------------------
__global__ void transpose_pad(const float* __restrict__ x) {
    __shared__ float tile[32][33];
    int b = blockIdx.z, i = blockIdx.y;
    int tj = blockIdx.x % 3;
    int tc = blockIdx.x / 3;
    int j0 = tj * 32, c0 = tc * 32;
    int tx = threadIdx.x, ty = threadIdx.y;   // 32 x 8

    const float* src = x + ((size_t)(b*C) * H + i) * W;
    #pragma unroll
    for (int q = 0; q < 4; q++) {
        int c = c0 + ty + q*8;
        tile[ty + q*8][tx] = src[(size_t)c * H * W + j0 + tx];
    }
    __syncthreads();
    float* dst = g_xp + (((size_t)b*HP) + (i+1)) * WP * C;
    #pragma unroll
    for (int q = 0; q < 4; q++) {
        int jj = j0 + ty + q*8;
        dst[(size_t)(jj+1)*C + c0 + tx] = tile[tx][ty + q*8];
    }
}

// ---------------- meta: offset conv + sigmoid + bilinear setup --------------
__global__ void meta_kernel(const float* __restrict__ pconv_b,
                            const float* __restrict__ adconv_b) {
    int gwarp = (blockIdx.x * blockDim.x + threadIdx.x) >> 5;
    int lane  = threadIdx.x & 31;
    if (gwarp >= NPIX) return;
    int pix = gwarp;
    int b = pix / (H*W);
    int rem = pix % (H*W);
    int i = rem / W;
    int j = rem % W;

    float part[21];
    #pragma unroll
    for (int f = 0; f < 21; f++) part[f] = 0.f;

    const float4* wm4 = (const float4*)g_wmeta;
    #pragma unroll
    for (int n = 0; n < 9; n++) {
        int kr = n / 3, kc = n % 3;
        const float4* xr = (const float4*)(g_xp + (size_t)(((b*HP) + (i+kr))*WP + (j+kc)) * C);
        float4 xv = xr[lane];
        const float4* wrow = wm4 + (size_t)(n*21)*32 + lane;
        #pragma unroll
        for (int f = 0; f < 21; f++) {
            float4 wv = wrow[(size_t)f*32];
            part[f] += xv.x*wv.x + xv.y*wv.y + xv.z*wv.z + xv.w*wv.w;
        }
    }
    #pragma unroll
    for (int f = 0; f < 21; f++) {
        #pragma unroll
        for (int s = 16; s; s >>= 1)
            part[f] += __shfl_xor_sync(0xffffffffu, part[f], s);
    }

    if (lane < 9) {
        int n = lane;
        float offx = part[n]     + pconv_b[n];
        float offy = part[9 + n] + pconv_b[9 + n];
        int m = n % 3;
        float adv = part[18 + m] + adconv_b[m];
        float adb = 1.f - 1.f / (1.f + expf(-adv));   // 1 - sigmoid
        float pnx = (float)(n / 3 - 1);
        float pny = (float)(n % 3 - 1);
        float px = (float)(i + 1) + pnx * (1.f + 2.f*adb) + offx;
        float py = (float)(j + 1) + pny * (1.f + 2.f*adb) + offy;

        float flx = floorf(px), fly = floorf(py);
        int qltx = min(max((int)flx,     0), HP-1);
        int qlty = min(max((int)fly,     0), WP-1);
        int qrbx = min(max((int)flx + 1, 0), HP-1);
        int qrby = min(max((int)fly + 1, 0), WP-1);
        bool mx = (px < 1.f) || (px > (float)(HP-2));
        bool my = (py < 1.f) || (py > (float)(WP-2));
        float pxe = mx ? fminf(fmaxf(flx, 0.f), (float)(HP-1)) : fminf(fmaxf(px, 0.f), (float)(HP-1));
        float pye = my ? fminf(fmaxf(fly, 0.f), (float)(WP-1)) : fminf(fmaxf(py, 0.f), (float)(WP-1));

        float glt_x = 1.f + ((float)qltx - pxe);
        float glt_y = 1.f + ((float)qlty - pye);
        float grb_x = 1.f - ((float)qrbx - pxe);
        float grb_y = 1.f - ((float)qrby - pye);

        float4 g = make_float4(glt_x*glt_y, grb_x*grb_y, glt_x*grb_y, grb_x*glt_y);
        int base = b * HP * WP;
        int4 idx = make_int4(base + qltx*WP + qlty,
                             base + qrbx*WP + qrby,
                             base + qltx*WP + qrby,
                             base + qrbx*WP + qlty);
        g_mg[pix*9 + n]   = g;
        g_midx[pix*9 + n] = idx;
    }
}

// ---------------- main gather-GEMM (FFMA2 inner loop) -----------------------
// out[o, p] = sum_n sum_c wg[n][c][o] * xoff[n][c][p]
// 256 threads; tile 128 o x 32 p; thread tile = 4 o (2 pairs) x 4 p; 8 FFMA2/k
__global__ void __launch_bounds__(256) main_kernel(float* __restrict__ out) {
    extern __shared__ char smem[];
    float4* sg    = (float4*)(smem + SG_OFF);
    int4*   sidx  = (int4*)  (smem + SIDX_OFF);
    char*   ws    = smem + WS_OFF;    // [c][o] fp32, 512B/row, full n-slab (64KB)
    char*   xsd   = smem + XSD_OFF;   // dup-pair pixel tile, 272B/row

    int tid = threadIdx.x;
    int tx = tid & 7;     // pixel group: pixels 4tx..4tx+3
    int ty = tid >> 3;    // o group: o = 4ty..4ty+3 (two FFMA2 pairs)
    int pt0 = blockIdx.x * PT;
    unsigned xoffb = (unsigned)(tx*32 + (tx>>2)*16);   // this thread's chunk byte offset

    unsigned long long acc[2][4];
    #pragma unroll
    for (int a = 0; a < 2; a++)
        #pragma unroll
        for (int q = 0; q < 4; q++) acc[a][q] = 0ULL;

    const float4* xp4 = (const float4*)g_xp;

    for (int n = 0; n < 9; n++) {
        __syncthreads();   // previous iteration done with sg/ws/xsd
        if (tid < PT) {
            sg[tid]   = g_mg[(size_t)(pt0 + tid)*9 + n];
            sidx[tid] = g_midx[(size_t)(pt0 + tid)*9 + n];
        }
        // stage full weight slab for this n: 16384 floats
        {
            const float4* srcw = (const float4*)(g_wg + (size_t)n*C*OCH);
            float4* dstw = (float4*)ws;
            #pragma unroll
            for (int t = 0; t < 16; t++)
                dstw[tid + t*256] = srcw[tid + t*256];
        }
        __syncthreads();   // sg visible

        // gather: thread (pl, cg) blends 16 channels for one pixel, stores dup pairs
        {
            int pl = tid >> 3;      // pixel 0..31
            int cg = tid & 7;       // channel-quad group 0..7
            float4 g = sg[pl];
            int4  id = sidx[pl];
            const float4* plt = xp4 + (size_t)id.x * 32;
            const float4* prb = xp4 + (size_t)id.y * 32;
            const float4* plb = xp4 + (size_t)id.z * 32;
            const float4* prt = xp4 + (size_t)id.w * 32;
            unsigned posb = (unsigned)((pl>>2)*32 + (pl>>4)*16 + (pl&3)*8);
            char* xrowp = xsd + posb;
            #pragma unroll
            for (int q = 0; q < 4; q++) {
                int c4 = cg*4 + q;
                float4 a = plt[c4], r = prb[c4], lb = plb[c4], rt = prt[c4];
                float4 v;
                v.x = g.x*a.x + g.y*r.x + g.z*lb.x + g.w*rt.x;
                v.y = g.x*a.y + g.y*r.y + g.z*lb.y + g.w*rt.y;
                v.z = g.x*a.z + g.y*r.z + g.z*lb.z + g.w*rt.z;
                v.w = g.x*a.w + g.y*r.w + g.z*lb.w + g.w*rt.w;
                int c = c4*4;
                *(unsigned long long*)(xrowp + (size_t)(c+0)*XSD_ROW) = dup2(v.x);
                *(unsigned long long*)(xrowp + (size_t)(c+1)*XSD_ROW) = dup2(v.y);
                *(unsigned long long*)(xrowp + (size_t)(c+2)*XSD_ROW) = dup2(v.z);
                *(unsigned long long*)(xrowp + (size_t)(c+3)*XSD_ROW) = dup2(v.w);
            }
        }
        __syncthreads();   // xsd + ws ready

        // K loop over 128 channels: 3 LDS.128 + 8 FFMA2 per k
        {
            const char* wp = ws + (size_t)ty*16;
            const char* xp = xsd + xoffb;
            #pragma unroll 8
            for (int k = 0; k < C; k++) {
                ulonglong2 wv = *(const ulonglong2*)(wp + (size_t)k*512);  // (w_o0,w_o1),(w_o2,w_o3)
                ulonglong2 xa = *(const ulonglong2*)(xp + (size_t)k*XSD_ROW);       // (x0,x0),(x1,x1)
                ulonglong2 xb = *(const ulonglong2*)(xp + (size_t)k*XSD_ROW + 16);  // (x2,x2),(x3,x3)
                FMA2(acc[0][0], wv.x, xa.x);
                FMA2(acc[0][1], wv.x, xa.y);
                FMA2(acc[0][2], wv.x, xb.x);
                FMA2(acc[0][3], wv.x, xb.y);
                FMA2(acc[1][0], wv.y, xa.x);
                FMA2(acc[1][1], wv.y, xa.y);
                FMA2(acc[1][2], wv.y, xb.x);
                FMA2(acc[1][3], wv.y, xb.y);
            }
        }
    }

    // write: 32 consecutive linear pixels (same b, same row i); float4 per o-row
    int b = pt0 / (H*W);
    int rem = pt0 % (H*W);
    int i = rem / W;
    int j0 = rem % W;
    #pragma unroll
    for (int op = 0; op < 2; op++) {
        int o0 = ty*4 + op*2;
        float* r0 = out + (((size_t)b*OCH + o0)*H + i)*W + j0 + tx*4;
        float* r1 = r0 + (size_t)H*W;   // o0+1
        float4 v0 = make_float4(u64lo(acc[op][0]), u64lo(acc[op][1]),
                                u64lo(acc[op][2]), u64lo(acc[op][3]));
        float4 v1 = make_float4(u64hi(acc[op][0]), u64hi(acc[op][1]),
                                u64hi(acc[op][2]), u64hi(acc[op][3]));
        *(float4*)r0 = v0;
        *(float4*)r1 = v1;
    }
}

// ---------------- launcher ---------------------------------------------------
extern "C" void kernel_launch(void* const* d_in, const int* in_sizes, int n_in,
                              void* d_out, int out_size) {
    const float* x        = (const float*)d_in[0];
    const float* conv_w   = (const float*)d_in[1];
    const float* pconv_w  = (const float*)d_in[2];
    const float* pconv_b  = (const float*)d_in[3];
    const float* adconv_w = (const float*)d_in[4];
    const float* adconv_b = (const float*)d_in[5];
    float* out = (float*)d_out;

    cudaFuncSetAttribute(main_kernel, cudaFuncAttributeMaxDynamicSharedMemorySize, SMEM_BYTES);

    prep_weights<<<576, 256>>>(conv_w, pconv_w, adconv_w);
    transpose_pad<<<dim3(12, 96, 2), dim3(32, 8)>>>(x);
    meta_kernel<<<NPIX/8, 256>>>(pconv_b, adconv_b);
    main_kernel<<<NPIX/PT, 256, SMEM_BYTES>>>(out);
}

// round 4
// speedup vs baseline: 1.2824x; 1.0885x over previous
#include <cuda_runtime.h>
#include <math.h>

#define H 96
#define W 96
#define C 128
#define OCH 128
#define BATCH 2
#define HP 98
#define WP 98
#define NPIX (BATCH*H*W)   // 18432
#define PT 32              // pixel tile for main GEMM
#define KCH 16             // k-chunk (channels) per weight stage
#define NCHUNK (C/KCH)     // 8 chunks per n

// xsd row layout: 8 chunks of 32B (4 pixels as dup-pairs), chunks 4..7 shifted +16B
// row stride = 272 bytes. POSB(p) = (p>>2)*32 + (p>>4)*16 + (p&3)*8
#define XSD_ROW 272

// dynamic smem layout (bytes)
#define SG_OFF    0
#define SIDX_OFF  512
#define WS_OFF    1024                     // 2 x 8KB weight chunk buffers
#define XSD_OFF   (1024 + 2*8192)          // 17408
#define SMEM_BYTES (XSD_OFF + C*XSD_ROW)   // 17408 + 34816 = 52224

// ---------------- scratch (device globals; no allocation allowed) ----------
__device__ float  g_xp[BATCH*HP*WP*C];     // padded NHWC input (~9.8MB, borders 0)
__device__ float  g_wg[9*C*OCH];           // main conv weights [n][c][o]
__device__ float  g_wmeta[9*21*C];         // meta conv weights [n][f][c]
__device__ float4 g_mg[NPIX*9];            // bilinear weights (lt, rb, lb, rt)
__device__ int4   g_midx[NPIX*9];          // flat gather indices into xp (pixel units)

// f32x2 packed FMA: d = a*b + d
#define FMA2(d, a, b) asm("fma.rn.f32x2 %0, %1, %2, %0;" : "+l"(d) : "l"(a), "l"(b))

static __device__ __forceinline__ unsigned long long dup2(float v) {
    unsigned long long r;
    asm("mov.b64 %0, {%1, %1};" : "=l"(r) : "f"(v));
    return r;
}
static __device__ __forceinline__ float u64lo(unsigned long long u) {
    return __uint_as_float((unsigned)(u & 0xffffffffu));
}
static __device__ __forceinline__ float u64hi(unsigned long long u) {
    return __uint_as_float((unsigned)(u >> 32));
}
static __device__ __forceinline__ void cp16(void* dst_smem, const void* src) {
    unsigned d = (unsigned)__cvta_generic_to_shared(dst_smem);
    asm volatile("cp.async.cg.shared.global [%0], [%1], 16;" :: "r"(d), "l"(src));
}
#define CP_COMMIT() asm volatile("cp.async.commit_group;")
#define CP_WAIT0()  asm volatile("cp.async.wait_group 0;")

// ---------------- weight prep ----------------------------------------------
__global__ void prep_weights(const float* __restrict__ conv_w,
                             const float* __restrict__ pconv_w,
                             const float* __restrict__ adconv_w) {
    int lin = blockIdx.x * blockDim.x + threadIdx.x;
    if (lin < 9*C*OCH) {
        int o = lin % OCH;
        int c = (lin / OCH) % C;
        int n = lin / (OCH*C);
        g_wg[lin] = conv_w[(o*C + c)*9 + n];
    }
    if (lin < 9*21*C) {
        int c = lin % C;
        int f = (lin / C) % 21;
        int n = lin / (21*C);
        g_wmeta[lin] = (f < 18) ? pconv_w[(f*C + c)*9 + n]
                                : adconv_w[((f-18)*C + c)*9 + n];
    }
}

// ---------------- NCHW -> padded NHWC transpose -----------------------------
__global__ void transpose_pad(const float* __restrict__ x) {
    __shared__ float tile[32][33];
    int b = blockIdx.z, i = blockIdx.y;
    int tj = blockIdx.x % 3;
    int tc = blockIdx.x / 3;
    int j0 = tj * 32, c0 = tc * 32;
    int tx = threadIdx.x, ty = threadIdx.y;   // 32 x 8

    const float* src = x + ((size_t)(b*C) * H + i) * W;
    #pragma unroll
    for (int q = 0; q < 4; q++) {
        int c = c0 + ty + q*8;
        tile[ty + q*8][tx] = src[(size_t)c * H * W + j0 + tx];
    }
    __syncthreads();
    float* dst = g_xp + (((size_t)b*HP) + (i+1)) * WP * C;
    #pragma unroll
    for (int q = 0; q < 4; q++) {
        int jj = j0 + ty + q*8;
        dst[(size_t)(jj+1)*C + c0 + tx] = tile[tx][ty + q*8];
    }
}

// ---------------- meta: offset conv + sigmoid + bilinear setup --------------
__global__ void meta_kernel(const float* __restrict__ pconv_b,
                            const float* __restrict__ adconv_b) {
    int gwarp = (blockIdx.x * blockDim.x + threadIdx.x) >> 5;
    int lane  = threadIdx.x & 31;
    if (gwarp >= NPIX) return;
    int pix = gwarp;
    int b = pix / (H*W);
    int rem = pix % (H*W);
    int i = rem / W;
    int j = rem % W;

    float part[21];
    #pragma unroll
    for (int f = 0; f < 21; f++) part[f] = 0.f;

    const float4* wm4 = (const float4*)g_wmeta;
    #pragma unroll
    for (int n = 0; n < 9; n++) {
        int kr = n / 3, kc = n % 3;
        const float4* xr = (const float4*)(g_xp + (size_t)(((b*HP) + (i+kr))*WP + (j+kc)) * C);
        float4 xv = xr[lane];
        const float4* wrow = wm4 + (size_t)(n*21)*32 + lane;
        #pragma unroll
        for (int f = 0; f < 21; f++) {
            float4 wv = wrow[(size_t)f*32];
            part[f] += xv.x*wv.x + xv.y*wv.y + xv.z*wv.z + xv.w*wv.w;
        }
    }
    #pragma unroll
    for (int f = 0; f < 21; f++) {
        #pragma unroll
        for (int s = 16; s; s >>= 1)
            part[f] += __shfl_xor_sync(0xffffffffu, part[f], s);
    }

    if (lane < 9) {
        int n = lane;
        float offx = part[n]     + pconv_b[n];
        float offy = part[9 + n] + pconv_b[9 + n];
        int m = n % 3;
        float adv = part[18 + m] + adconv_b[m];
        float adb = 1.f - 1.f / (1.f + expf(-adv));   // 1 - sigmoid
        float pnx = (float)(n / 3 - 1);
        float pny = (float)(n % 3 - 1);
        float px = (float)(i + 1) + pnx * (1.f + 2.f*adb) + offx;
        float py = (float)(j + 1) + pny * (1.f + 2.f*adb) + offy;

        float flx = floorf(px), fly = floorf(py);
        int qltx = min(max((int)flx,     0), HP-1);
        int qlty = min(max((int)fly,     0), WP-1);
        int qrbx = min(max((int)flx + 1, 0), HP-1);
        int qrby = min(max((int)fly + 1, 0), WP-1);
        bool mx = (px < 1.f) || (px > (float)(HP-2));
        bool my = (py < 1.f) || (py > (float)(WP-2));
        float pxe = mx ? fminf(fmaxf(flx, 0.f), (float)(HP-1)) : fminf(fmaxf(px, 0.f), (float)(HP-1));
        float pye = my ? fminf(fmaxf(fly, 0.f), (float)(WP-1)) : fminf(fmaxf(py, 0.f), (float)(WP-1));

        float glt_x = 1.f + ((float)qltx - pxe);
        float glt_y = 1.f + ((float)qlty - pye);
        float grb_x = 1.f - ((float)qrbx - pxe);
        float grb_y = 1.f - ((float)qrby - pye);

        float4 g = make_float4(glt_x*glt_y, grb_x*grb_y, glt_x*grb_y, grb_x*glt_y);
        int base = b * HP * WP;
        int4 idx = make_int4(base + qltx*WP + qlty,
                             base + qrbx*WP + qrby,
                             base + qltx*WP + qrby,
                             base + qrbx*WP + qlty);
        g_mg[pix*9 + n]   = g;
        g_midx[pix*9 + n] = idx;
    }
}

// ---------------- main gather-GEMM (FFMA2 + cp.async pipeline) --------------
// out[o, p] = sum_n sum_c wg[n][c][o] * xoff[n][c][p]
// 256 threads; tile 128 o x 32 p; thread tile 4 o (2 pairs) x 4 p; 8 FFMA2/k
__global__ void __launch_bounds__(256, 4) main_kernel(float* __restrict__ out) {
    extern __shared__ char smem[];
    float4* sg    = (float4*)(smem + SG_OFF);
    int4*   sidx  = (int4*)  (smem + SIDX_OFF);
    char*   ws    = smem + WS_OFF;    // 2 x [16 c][128 o] fp32 chunk buffers
    char*   xsd   = smem + XSD_OFF;   // dup-pair pixel tile, 272B/row

    int tid = threadIdx.x;
    int tx = tid & 7;     // pixel group: pixels 4tx..4tx+3
    int ty = tid >> 3;    // o group: o = 4ty..4ty+3 (two FFMA2 pairs)
    int pt0 = blockIdx.x * PT;
    unsigned xoffb = (unsigned)(tx*32 + (tx>>2)*16);

    unsigned long long acc[2][4];
    #pragma unroll
    for (int a = 0; a < 2; a++)
        #pragma unroll
        for (int q = 0; q < 4; q++) acc[a][q] = 0ULL;

    const float4* xp4 = (const float4*)g_xp;

    for (int n = 0; n < 9; n++) {
        __syncthreads();   // all warps done with ws bufs + xsd + sg from prev n
        if (tid < PT) {
            sg[tid]   = g_mg[(size_t)(pt0 + tid)*9 + n];
            sidx[tid] = g_midx[(size_t)(pt0 + tid)*9 + n];
        }
        // prefetch weight chunk 0 for this n (overlaps with gather below)
        {
            const float4* srcw = (const float4*)(g_wg + (size_t)n*C*OCH);
            float4* dstw = (float4*)ws;
            cp16(dstw + tid,       srcw + tid);
            cp16(dstw + tid + 256, srcw + tid + 256);
            CP_COMMIT();
        }
        __syncthreads();   // sg/sidx visible

        // gather: thread (pl, cg) blends 16 channels for one pixel, stores dup pairs
        {
            int pl = tid >> 3;
            int cg = tid & 7;
            float4 g = sg[pl];
            int4  id = sidx[pl];
            const float4* plt = xp4 + (size_t)id.x * 32;
            const float4* prb = xp4 + (size_t)id.y * 32;
            const float4* plb = xp4 + (size_t)id.z * 32;
            const float4* prt = xp4 + (size_t)id.w * 32;
            unsigned posb = (unsigned)((pl>>2)*32 + (pl>>4)*16 + (pl&3)*8);
            char* xrowp = xsd + posb;
            #pragma unroll
            for (int q = 0; q < 4; q++) {
                int c4 = cg*4 + q;
                float4 a = plt[c4], r = prb[c4], lb = plb[c4], rt = prt[c4];
                float4 v;
                v.x = g.x*a.x + g.y*r.x + g.z*lb.x + g.w*rt.x;
                v.y = g.x*a.y + g.y*r.y + g.z*lb.y + g.w*rt.y;
                v.z = g.x*a.z + g.y*r.z + g.z*lb.z + g.w*rt.z;
                v.w = g.x*a.w + g.y*r.w + g.z*lb.w + g.w*rt.w;
                int c = c4*4;
                *(unsigned long long*)(xrowp + (size_t)(c+0)*XSD_ROW) = dup2(v.x);
                *(unsigned long long*)(xrowp + (size_t)(c+1)*XSD_ROW) = dup2(v.y);
                *(unsigned long long*)(xrowp + (size_t)(c+2)*XSD_ROW) = dup2(v.z);
                *(unsigned long long*)(xrowp + (size_t)(c+3)*XSD_ROW) = dup2(v.w);
            }
        }

        // chunked K loop with double-buffered cp.async weight staging
        #pragma unroll 1
        for (int kc = 0; kc < NCHUNK; kc++) {
            CP_WAIT0();        // chunk kc landed
            __syncthreads();   // + all warps done with the buffer we overwrite next
            if (kc + 1 < NCHUNK) {
                const float4* srcw = (const float4*)(g_wg + (size_t)n*C*OCH + (size_t)(kc+1)*KCH*OCH);
                float4* dstw = (float4*)(ws + ((kc+1)&1)*8192);
                cp16(dstw + tid,       srcw + tid);
                cp16(dstw + tid + 256, srcw + tid + 256);
                CP_COMMIT();
            }
            const char* wp = ws + (kc&1)*8192 + (size_t)ty*16;
            const char* xp = xsd + xoffb + (size_t)kc*KCH*XSD_ROW;
            #pragma unroll
            for (int k = 0; k < KCH; k++) {
                ulonglong2 wv = *(const ulonglong2*)(wp + (size_t)k*512);
                ulonglong2 xa = *(const ulonglong2*)(xp + (size_t)k*XSD_ROW);
                ulonglong2 xb = *(const ulonglong2*)(xp + (size_t)k*XSD_ROW + 16);
                FMA2(acc[0][0], wv.x, xa.x);
                FMA2(acc[0][1], wv.x, xa.y);
                FMA2(acc[0][2], wv.x, xb.x);
                FMA2(acc[0][3], wv.x, xb.y);
                FMA2(acc[1][0], wv.y, xa.x);
                FMA2(acc[1][1], wv.y, xa.y);
                FMA2(acc[1][2], wv.y, xb.x);
                FMA2(acc[1][3], wv.y, xb.y);
            }
        }
    }

    // write: 32 consecutive linear pixels (same b, same row i); float4 per o-row
    int b = pt0 / (H*W);
    int rem = pt0 % (H*W);
    int i = rem / W;
    int j0 = rem % W;
    #pragma unroll
    for (int op = 0; op < 2; op++) {
        int o0 = ty*4 + op*2;
        float* r0 = out + (((size_t)b*OCH + o0)*H + i)*W + j0 + tx*4;
        float* r1 = r0 + (size_t)H*W;
        float4 v0 = make_float4(u64lo(acc[op][0]), u64lo(acc[op][1]),
                                u64lo(acc[op][2]), u64lo(acc[op][3]));
        float4 v1 = make_float4(u64hi(acc[op][0]), u64hi(acc[op][1]),
                                u64hi(acc[op][2]), u64hi(acc[op][3]));
        *(float4*)r0 = v0;
        *(float4*)r1 = v1;
    }
}

// ---------------- launcher ---------------------------------------------------
extern "C" void kernel_launch(void* const* d_in, const int* in_sizes, int n_in,
                              void* d_out, int out_size) {
    const float* x        = (const float*)d_in[0];
    const float* conv_w   = (const float*)d_in[1];
    const float* pconv_w  = (const float*)d_in[2];
    const float* pconv_b  = (const float*)d_in[3];
    const float* adconv_w = (const float*)d_in[4];
    const float* adconv_b = (const float*)d_in[5];
    float* out = (float*)d_out;

    cudaFuncSetAttribute(main_kernel, cudaFuncAttributeMaxDynamicSharedMemorySize, SMEM_BYTES);

    prep_weights<<<576, 256>>>(conv_w, pconv_w, adconv_w);
    transpose_pad<<<dim3(12, 96, 2), dim3(32, 8)>>>(x);
    meta_kernel<<<NPIX/8, 256>>>(pconv_b, adconv_b);
    main_kernel<<<NPIX/PT, 256, SMEM_BYTES>>>(out);
}

// round 5
// speedup vs baseline: 1.6181x; 1.2617x over previous
#include <cuda_runtime.h>
#include <math.h>

#define H 96
#define W 96
#define C 128
#define OCH 128
#define BATCH 2
#define HP 98
#define WP 98
#define NPIX (BATCH*H*W)   // 18432
#define PT 32              // pixel tile
#define KCH 16             // channels per weight stage chunk
#define NCHUNK (C/KCH)     // 8
#define NKK 64             // k-pairs per n (C/2)

#define XROW 264           // bytes per k-pair row in xs (32 px * 8B + 8 pad)

// ---------------- scratch (device globals; no allocation allowed) ----------
__device__ float  g_xp[BATCH*HP*WP*C];     // padded NHWC input (~9.8MB, borders 0)
__device__ float2 g_wg2[9*NKK*OCH];        // weights [n][kpair][o] = (w_even, w_odd)
__device__ float  g_wmeta[9*21*C];         // meta conv weights [n][f][c]
__device__ float4 g_mg[NPIX*9];            // bilinear weights (lt, rb, lb, rt)
__device__ int4   g_midx[NPIX*9];          // flat gather indices into xp (pixel units)

// f32x2 packed FMA: d = a*b + d (two independent fp32 lanes)
#define FMA2(d, a, b) asm("fma.rn.f32x2 %0, %1, %2, %0;" : "+l"(d) : "l"(a), "l"(b))

static __device__ __forceinline__ float u64lo(unsigned long long u) {
    return __uint_as_float((unsigned)(u & 0xffffffffu));
}
static __device__ __forceinline__ float u64hi(unsigned long long u) {
    return __uint_as_float((unsigned)(u >> 32));
}
static __device__ __forceinline__ void cp16(void* dst_smem, const void* src) {
    unsigned d = (unsigned)__cvta_generic_to_shared(dst_smem);
    asm volatile("cp.async.cg.shared.global [%0], [%1], 16;" :: "r"(d), "l"(src));
}
#define CP_COMMIT() asm volatile("cp.async.commit_group;")
#define CP_WAIT0()  asm volatile("cp.async.wait_group 0;")

// ---------------- weight prep ----------------------------------------------
__global__ void prep_weights(const float* __restrict__ conv_w,
                             const float* __restrict__ pconv_w,
                             const float* __restrict__ adconv_w) {
    int lin = blockIdx.x * blockDim.x + threadIdx.x;
    if (lin < 9*NKK*OCH) {
        int o  = lin % OCH;
        int kk = (lin / OCH) % NKK;
        int n  = lin / (OCH*NKK);
        float lo = conv_w[(o*C + 2*kk)*9 + n];
        float hi = conv_w[(o*C + 2*kk + 1)*9 + n];
        g_wg2[lin] = make_float2(lo, hi);
    }
    if (lin < 9*21*C) {
        int c = lin % C;
        int f = (lin / C) % 21;
        int n = lin / (21*C);
        g_wmeta[lin] = (f < 18) ? pconv_w[(f*C + c)*9 + n]
                                : adconv_w[((f-18)*C + c)*9 + n];
    }
}

// ---------------- NCHW -> padded NHWC transpose -----------------------------
__global__ void transpose_pad(const float* __restrict__ x) {
    __shared__ float tile[32][33];
    int b = blockIdx.z, i = blockIdx.y;
    int tj = blockIdx.x % 3;
    int tc = blockIdx.x / 3;
    int j0 = tj * 32, c0 = tc * 32;
    int tx = threadIdx.x, ty = threadIdx.y;   // 32 x 8

    const float* src = x + ((size_t)(b*C) * H + i) * W;
    #pragma unroll
    for (int q = 0; q < 4; q++) {
        int c = c0 + ty + q*8;
        tile[ty + q*8][tx] = src[(size_t)c * H * W + j0 + tx];
    }
    __syncthreads();
    float* dst = g_xp + (((size_t)b*HP) + (i+1)) * WP * C;
    #pragma unroll
    for (int q = 0; q < 4; q++) {
        int jj = j0 + ty + q*8;
        dst[(size_t)(jj+1)*C + c0 + tx] = tile[tx][ty + q*8];
    }
}

// ---------------- meta: offset conv + sigmoid + bilinear setup --------------
__global__ void meta_kernel(const float* __restrict__ pconv_b,
                            const float* __restrict__ adconv_b) {
    int gwarp = (blockIdx.x * blockDim.x + threadIdx.x) >> 5;
    int lane  = threadIdx.x & 31;
    if (gwarp >= NPIX) return;
    int pix = gwarp;
    int b = pix / (H*W);
    int rem = pix % (H*W);
    int i = rem / W;
    int j = rem % W;

    float part[21];
    #pragma unroll
    for (int f = 0; f < 21; f++) part[f] = 0.f;

    const float4* wm4 = (const float4*)g_wmeta;
    #pragma unroll
    for (int n = 0; n < 9; n++) {
        int kr = n / 3, kc = n % 3;
        const float4* xr = (const float4*)(g_xp + (size_t)(((b*HP) + (i+kr))*WP + (j+kc)) * C);
        float4 xv = xr[lane];
        const float4* wrow = wm4 + (size_t)(n*21)*32 + lane;
        #pragma unroll
        for (int f = 0; f < 21; f++) {
            float4 wv = wrow[(size_t)f*32];
            part[f] += xv.x*wv.x + xv.y*wv.y + xv.z*wv.z + xv.w*wv.w;
        }
    }
    #pragma unroll
    for (int f = 0; f < 21; f++) {
        #pragma unroll
        for (int s = 16; s; s >>= 1)
            part[f] += __shfl_xor_sync(0xffffffffu, part[f], s);
    }

    if (lane < 9) {
        int n = lane;
        float offx = part[n]     + pconv_b[n];
        float offy = part[9 + n] + pconv_b[9 + n];
        int m = n % 3;
        float adv = part[18 + m] + adconv_b[m];
        float adb = 1.f - 1.f / (1.f + expf(-adv));   // 1 - sigmoid
        float pnx = (float)(n / 3 - 1);
        float pny = (float)(n % 3 - 1);
        float px = (float)(i + 1) + pnx * (1.f + 2.f*adb) + offx;
        float py = (float)(j + 1) + pny * (1.f + 2.f*adb) + offy;

        float flx = floorf(px), fly = floorf(py);
        int qltx = min(max((int)flx,     0), HP-1);
        int qlty = min(max((int)fly,     0), WP-1);
        int qrbx = min(max((int)flx + 1, 0), HP-1);
        int qrby = min(max((int)fly + 1, 0), WP-1);
        bool mx = (px < 1.f) || (px > (float)(HP-2));
        bool my = (py < 1.f) || (py > (float)(WP-2));
        float pxe = mx ? fminf(fmaxf(flx, 0.f), (float)(HP-1)) : fminf(fmaxf(px, 0.f), (float)(HP-1));
        float pye = my ? fminf(fmaxf(fly, 0.f), (float)(WP-1)) : fminf(fmaxf(py, 0.f), (float)(WP-1));

        float glt_x = 1.f + ((float)qltx - pxe);
        float glt_y = 1.f + ((float)qlty - pye);
        float grb_x = 1.f - ((float)qrbx - pxe);
        float grb_y = 1.f - ((float)qrby - pye);

        float4 g = make_float4(glt_x*glt_y, grb_x*grb_y, glt_x*grb_y, grb_x*glt_y);
        int base = b * HP * WP;
        int4 idx = make_int4(base + qltx*WP + qlty,
                             base + qrbx*WP + qrby,
                             base + qltx*WP + qrby,
                             base + qrbx*WP + qlty);
        g_mg[pix*9 + n]   = g;
        g_midx[pix*9 + n] = idx;
    }
}

// ---------------- main gather-GEMM (k-paired FFMA2) -------------------------
// acc2[o][p] accumulates (sum over even c, sum over odd c); final = lo + hi.
// 128 threads; block tile 128 o x 32 p; thread tile 8 o x 4 p; 32 FFMA2 / 2k.
__global__ void __launch_bounds__(128) main_kernel(float* __restrict__ out) {
    __shared__ float4 sg[PT];
    __shared__ int4   sidx[PT];
    __shared__ char   wsb[2*8192];       // 2 x [8 kk][128 o] u64 weight chunks
    __shared__ char   xsb[NKK*XROW];     // x pairs: [kk][perm(p)] u64, 264B rows

    int tid = threadIdx.x;
    int tx = tid & 7;     // pixel group: pixels tx*4 .. tx*4+3
    int ty = tid >> 3;    // o group: o = ty*8 .. ty*8+7
    int pt0 = blockIdx.x * PT;

    unsigned long long acc2[8][4];
    #pragma unroll
    for (int a = 0; a < 8; a++)
        #pragma unroll
        for (int q = 0; q < 4; q++) acc2[a][q] = 0ULL;

    const float4* xp4 = (const float4*)g_xp;

    for (int n = 0; n < 9; n++) {
        __syncthreads();   // everyone done with sg/wsb/xsb from prev n
        if (tid < PT) {
            sg[tid]   = g_mg[(size_t)(pt0 + tid)*9 + n];
            sidx[tid] = g_midx[(size_t)(pt0 + tid)*9 + n];
        }
        // prefetch weight chunk 0 for this n (overlaps gather)
        {
            const float4* srcw = (const float4*)(g_wg2 + (size_t)n*NKK*OCH);
            float4* dstw = (float4*)wsb;
            cp16(dstw + tid,       srcw + tid);
            cp16(dstw + tid + 128, srcw + tid + 128);
            cp16(dstw + tid + 256, srcw + tid + 256);
            cp16(dstw + tid + 384, srcw + tid + 384);
            CP_COMMIT();
        }
        __syncthreads();   // sg/sidx visible

        // gather: 4 threads per pixel, 32 channels each; write k-pair rows
        {
            int pl = tid >> 2;      // pixel 0..31
            int ch = tid & 3;       // channel chunk 0..3 (32 channels)
            float4 g = sg[pl];
            int4  id = sidx[pl];
            const float4* plt = xp4 + (size_t)id.x * 32;
            const float4* prb = xp4 + (size_t)id.y * 32;
            const float4* plb = xp4 + (size_t)id.z * 32;
            const float4* prt = xp4 + (size_t)id.w * 32;
            int pp = (pl & 3) * 8 + (pl >> 2);    // bank-friendly pixel permutation
            char* xc = xsb + pp * 8;
            #pragma unroll
            for (int q = 0; q < 8; q++) {
                int c4 = ch*8 + q;                // float4 index: channels 4c4..4c4+3
                float4 a = plt[c4], r = prb[c4], lb = plb[c4], rt = prt[c4];
                float4 v;
                v.x = g.x*a.x + g.y*r.x + g.z*lb.x + g.w*rt.x;
                v.y = g.x*a.y + g.y*r.y + g.z*lb.y + g.w*rt.y;
                v.z = g.x*a.z + g.y*r.z + g.z*lb.z + g.w*rt.z;
                v.w = g.x*a.w + g.y*r.w + g.z*lb.w + g.w*rt.w;
                int kk0 = c4 * 2;
                *(float2*)(xc + (size_t)kk0*XROW)       = make_float2(v.x, v.y);
                *(float2*)(xc + (size_t)(kk0+1)*XROW)   = make_float2(v.z, v.w);
            }
        }

        // chunked K loop, double-buffered cp.async weight staging
        #pragma unroll 1
        for (int kc = 0; kc < NCHUNK; kc++) {
            CP_WAIT0();
            __syncthreads();   // chunk kc landed; prev buffer free; (kc==0: gather done)
            if (kc + 1 < NCHUNK) {
                const float4* srcw = (const float4*)(g_wg2 + (size_t)n*NKK*OCH + (size_t)(kc+1)*8*OCH);
                float4* dstw = (float4*)(wsb + ((kc+1)&1)*8192);
                cp16(dstw + tid,       srcw + tid);
                cp16(dstw + tid + 128, srcw + tid + 128);
                cp16(dstw + tid + 256, srcw + tid + 256);
                cp16(dstw + tid + 384, srcw + tid + 384);
                CP_COMMIT();
            }
            const char* wchunk = wsb + (kc&1)*8192 + (size_t)ty*64;
            const char* xchunk = xsb + (size_t)(kc*8)*XROW + (size_t)tx*8;
            #pragma unroll
            for (int m = 0; m < 8; m++) {
                const char* wb = wchunk + (size_t)m*1024;
                ulonglong2 wv0 = *(const ulonglong2*)(wb);
                ulonglong2 wv1 = *(const ulonglong2*)(wb + 16);
                ulonglong2 wv2 = *(const ulonglong2*)(wb + 32);
                ulonglong2 wv3 = *(const ulonglong2*)(wb + 48);
                const char* xb = xchunk + (size_t)m*XROW;
                unsigned long long x0 = *(const unsigned long long*)(xb);
                unsigned long long x1 = *(const unsigned long long*)(xb + 64);
                unsigned long long x2 = *(const unsigned long long*)(xb + 128);
                unsigned long long x3 = *(const unsigned long long*)(xb + 192);
                FMA2(acc2[0][0], wv0.x, x0); FMA2(acc2[0][1], wv0.x, x1);
                FMA2(acc2[0][2], wv0.x, x2); FMA2(acc2[0][3], wv0.x, x3);
                FMA2(acc2[1][0], wv0.y, x0); FMA2(acc2[1][1], wv0.y, x1);
                FMA2(acc2[1][2], wv0.y, x2); FMA2(acc2[1][3], wv0.y, x3);
                FMA2(acc2[2][0], wv1.x, x0); FMA2(acc2[2][1], wv1.x, x1);
                FMA2(acc2[2][2], wv1.x, x2); FMA2(acc2[2][3], wv1.x, x3);
                FMA2(acc2[3][0], wv1.y, x0); FMA2(acc2[3][1], wv1.y, x1);
                FMA2(acc2[3][2], wv1.y, x2); FMA2(acc2[3][3], wv1.y, x3);
                FMA2(acc2[4][0], wv2.x, x0); FMA2(acc2[4][1], wv2.x, x1);
                FMA2(acc2[4][2], wv2.x, x2); FMA2(acc2[4][3], wv2.x, x3);
                FMA2(acc2[5][0], wv2.y, x0); FMA2(acc2[5][1], wv2.y, x1);
                FMA2(acc2[5][2], wv2.y, x2); FMA2(acc2[5][3], wv2.y, x3);
                FMA2(acc2[6][0], wv3.x, x0); FMA2(acc2[6][1], wv3.x, x1);
                FMA2(acc2[6][2], wv3.x, x2); FMA2(acc2[6][3], wv3.x, x3);
                FMA2(acc2[7][0], wv3.y, x0); FMA2(acc2[7][1], wv3.y, x1);
                FMA2(acc2[7][2], wv3.y, x2); FMA2(acc2[7][3], wv3.y, x3);
            }
        }
    }

    // epilogue: out = lo + hi (even + odd channel sums)
    int b = pt0 / (H*W);
    int rem = pt0 % (H*W);
    int i = rem / W;
    int j0 = rem % W;
    #pragma unroll
    for (int oo = 0; oo < 8; oo++) {
        int o = ty*8 + oo;
        float4 v;
        v.x = u64lo(acc2[oo][0]) + u64hi(acc2[oo][0]);
        v.y = u64lo(acc2[oo][1]) + u64hi(acc2[oo][1]);
        v.z = u64lo(acc2[oo][2]) + u64hi(acc2[oo][2]);
        v.w = u64lo(acc2[oo][3]) + u64hi(acc2[oo][3]);
        *(float4*)(out + (((size_t)b*OCH + o)*H + i)*W + j0 + tx*4) = v;
    }
}

// ---------------- launcher ---------------------------------------------------
extern "C" void kernel_launch(void* const* d_in, const int* in_sizes, int n_in,
                              void* d_out, int out_size) {
    const float* x        = (const float*)d_in[0];
    const float* conv_w   = (const float*)d_in[1];
    const float* pconv_w  = (const float*)d_in[2];
    const float* pconv_b  = (const float*)d_in[3];
    const float* adconv_w = (const float*)d_in[4];
    const float* adconv_b = (const float*)d_in[5];
    float* out = (float*)d_out;

    prep_weights<<<288, 256>>>(conv_w, pconv_w, adconv_w);
    transpose_pad<<<dim3(12, 96, 2), dim3(32, 8)>>>(x);
    meta_kernel<<<NPIX/8, 256>>>(pconv_b, adconv_b);
    main_kernel<<<NPIX/PT, 128>>>(out);
}

// round 8
// speedup vs baseline: 2.1473x; 1.3271x over previous
#include <cuda_runtime.h>
#include <math.h>
#include <stdint.h>

#define H 96
#define W 96
#define C 128
#define OCH 128
#define BATCH 2
#define HP 98
#define WP 98
#define HWIMG (H*W)              // 9216
#define NPIX (BATCH*H*W)         // 18432
#define PT 128                   // pixels per block
#define NBLK (NPIX/PT)           // 144

#define XS 272                   // smem row stride (128 bf16 = 256B data + 16B pad)
#define TS (128*XS)              // one 128x128 bf16 tile in smem = 34816B

// dynamic smem layout (byte offsets)
#define SM_SG    0               // float4[128]
#define SM_SIDX  2048            // int4[128]
#define SM_WHI   4096
#define SM_WLO   (SM_WHI + TS)
#define SM_XHI   (SM_WLO + TS)
#define SM_XLO   (SM_XHI + TS)
#define SMEM_BYTES (SM_XLO + TS)   // 4096 + 4*34816 = 143360

// ---------------- scratch (device globals; no allocation allowed) ----------
__device__ float    g_xp[BATCH*HP*WP*C];   // padded NHWC input (~9.8MB, borders 0)
__device__ uint32_t g_wbf2[9*2*128*64];    // [n][hi/lo][o][kpair] bf16x2 weights
__device__ float    g_wmeta[9*21*C];       // meta conv weights [n][f][c]
__device__ float4   g_mg[NPIX*9];          // bilinear weights (lt, rb, lb, rt)
__device__ int4     g_midx[NPIX*9];        // flat gather indices into xp (pixel units)

// ---------------- helpers ----------------------------------------------------
static __device__ __forceinline__ uint32_t smem_u32(const void* p) {
    uint32_t a;
    asm("{ .reg .u64 t; cvta.to.shared.u64 t, %1; cvt.u32.u64 %0, t; }" : "=r"(a) : "l"(p));
    return a;
}
static __device__ __forceinline__ void cp16(uint32_t dst_smem, const void* src) {
    asm volatile("cp.async.cg.shared.global [%0], [%1], 16;" :: "r"(dst_smem), "l"(src));
}
#define CP_COMMIT() asm volatile("cp.async.commit_group;")
#define CP_WAIT0()  asm volatile("cp.async.wait_group 0;")

static __device__ __forceinline__ uint32_t pack_bf16x2(float hi, float lo) {
    uint32_t r;
    asm("cvt.rn.bf16x2.f32 %0, %1, %2;" : "=r"(r) : "f"(hi), "f"(lo));
    return r;
}
static __device__ __forceinline__ float bf16hi_f(uint32_t p) { return __uint_as_float(p & 0xffff0000u); }
static __device__ __forceinline__ float bf16lo_f(uint32_t p) { return __uint_as_float(p << 16); }

static __device__ __forceinline__ void ldsm4(uint32_t a, uint32_t& r0, uint32_t& r1,
                                             uint32_t& r2, uint32_t& r3) {
    asm volatile("ldmatrix.sync.aligned.m8n8.x4.shared.b16 {%0,%1,%2,%3}, [%4];"
                 : "=r"(r0), "=r"(r1), "=r"(r2), "=r"(r3) : "r"(a));
}
static __device__ __forceinline__ void mma16816(float* d, const uint32_t* a,
                                                const uint32_t* b) {
    asm volatile("mma.sync.aligned.m16n8k16.row.col.f32.bf16.bf16.f32 "
                 "{%0,%1,%2,%3}, {%4,%5,%6,%7}, {%8,%9}, {%0,%1,%2,%3};"
                 : "+f"(d[0]), "+f"(d[1]), "+f"(d[2]), "+f"(d[3])
                 : "r"(a[0]), "r"(a[1]), "r"(a[2]), "r"(a[3]), "r"(b[0]), "r"(b[1]));
}

// ---------------- weight prep ----------------------------------------------
__global__ void prep_weights(const float* __restrict__ conv_w,
                             const float* __restrict__ pconv_w,
                             const float* __restrict__ adconv_w) {
    int lin = blockIdx.x * blockDim.x + threadIdx.x;
    if (lin < 9*128*64) {                     // (n, o, kpair)
        int kp = lin & 63;
        int o  = (lin >> 6) & 127;
        int n  = lin >> 13;
        float w0 = conv_w[(o*C + 2*kp)*9 + n];
        float w1 = conv_w[(o*C + 2*kp + 1)*9 + n];
        uint32_t phi = pack_bf16x2(w1, w0);   // lo16 = even channel
        float l0 = w0 - bf16lo_f(phi);
        float l1 = w1 - bf16hi_f(phi);
        uint32_t plo = pack_bf16x2(l1, l0);
        g_wbf2[(((size_t)n*2 + 0)*128 + o)*64 + kp] = phi;
        g_wbf2[(((size_t)n*2 + 1)*128 + o)*64 + kp] = plo;
    }
    if (lin < 9*21*C) {
        int c = lin % C;
        int f = (lin / C) % 21;
        int n = lin / (21*C);
        g_wmeta[lin] = (f < 18) ? pconv_w[(f*C + c)*9 + n]
                                : adconv_w[((f-18)*C + c)*9 + n];
    }
}

// ---------------- NCHW -> padded NHWC transpose -----------------------------
__global__ void transpose_pad(const float* __restrict__ x) {
    __shared__ float tile[32][33];
    int b = blockIdx.z, i = blockIdx.y;
    int tj = blockIdx.x % 3;
    int tc = blockIdx.x / 3;
    int j0 = tj * 32, c0 = tc * 32;
    int tx = threadIdx.x, ty = threadIdx.y;   // 32 x 8

    const float* src = x + ((size_t)(b*C) * H + i) * W;
    #pragma unroll
    for (int q = 0; q < 4; q++) {
        int c = c0 + ty + q*8;
        tile[ty + q*8][tx] = src[(size_t)c * H * W + j0 + tx];
    }
    __syncthreads();
    float* dst = g_xp + (((size_t)b*HP) + (i+1)) * WP * C;
    #pragma unroll
    for (int q = 0; q < 4; q++) {
        int jj = j0 + ty + q*8;
        dst[(size_t)(jj+1)*C + c0 + tx] = tile[tx][ty + q*8];
    }
}

// ---------------- meta: offset conv + sigmoid + bilinear setup --------------
__global__ void meta_kernel(const float* __restrict__ pconv_b,
                            const float* __restrict__ adconv_b) {
    int gwarp = (blockIdx.x * blockDim.x + threadIdx.x) >> 5;
    int lane  = threadIdx.x & 31;
    if (gwarp >= NPIX) return;
    int pix = gwarp;
    int b = pix / (H*W);
    int rem = pix % (H*W);
    int i = rem / W;
    int j = rem % W;

    float part[21];
    #pragma unroll
    for (int f = 0; f < 21; f++) part[f] = 0.f;

    const float4* wm4 = (const float4*)g_wmeta;
    #pragma unroll
    for (int n = 0; n < 9; n++) {
        int kr = n / 3, kc = n % 3;
        const float4* xr = (const float4*)(g_xp + (size_t)(((b*HP) + (i+kr))*WP + (j+kc)) * C);
        float4 xv = xr[lane];
        const float4* wrow = wm4 + (size_t)(n*21)*32 + lane;
        #pragma unroll
        for (int f = 0; f < 21; f++) {
            float4 wv = wrow[(size_t)f*32];
            part[f] += xv.x*wv.x + xv.y*wv.y + xv.z*wv.z + xv.w*wv.w;
        }
    }
    #pragma unroll
    for (int f = 0; f < 21; f++) {
        #pragma unroll
        for (int s = 16; s; s >>= 1)
            part[f] += __shfl_xor_sync(0xffffffffu, part[f], s);
    }

    if (lane < 9) {
        int n = lane;
        float offx = part[n]     + pconv_b[n];
        float offy = part[9 + n] + pconv_b[9 + n];
        int m = n % 3;
        float adv = part[18 + m] + adconv_b[m];
        float adb = 1.f - 1.f / (1.f + expf(-adv));   // 1 - sigmoid
        float pnx = (float)(n / 3 - 1);
        float pny = (float)(n % 3 - 1);
        float px = (float)(i + 1) + pnx * (1.f + 2.f*adb) + offx;
        float py = (float)(j + 1) + pny * (1.f + 2.f*adb) + offy;

        float flx = floorf(px), fly = floorf(py);
        int qltx = min(max((int)flx,     0), HP-1);
        int qlty = min(max((int)fly,     0), WP-1);
        int qrbx = min(max((int)flx + 1, 0), HP-1);
        int qrby = min(max((int)fly + 1, 0), WP-1);
        bool mx = (px < 1.f) || (px > (float)(HP-2));
        bool my = (py < 1.f) || (py > (float)(WP-2));
        float pxe = mx ? fminf(fmaxf(flx, 0.f), (float)(HP-1)) : fminf(fmaxf(px, 0.f), (float)(HP-1));
        float pye = my ? fminf(fmaxf(fly, 0.f), (float)(WP-1)) : fminf(fmaxf(py, 0.f), (float)(WP-1));

        float glt_x = 1.f + ((float)qltx - pxe);
        float glt_y = 1.f + ((float)qlty - pye);
        float grb_x = 1.f - ((float)qrbx - pxe);
        float grb_y = 1.f - ((float)qrby - pye);

        float4 g = make_float4(glt_x*glt_y, grb_x*grb_y, glt_x*grb_y, grb_x*glt_y);
        int base = b * HP * WP;
        int4 idx = make_int4(base + qltx*WP + qlty,
                             base + qrbx*WP + qrby,
                             base + qltx*WP + qrby,
                             base + qrbx*WP + qlty);
        g_mg[pix*9 + n]   = g;
        g_midx[pix*9 + n] = idx;
    }
}

// ---------------- main: mma.sync bf16-split gather-GEMM ---------------------
// D[128 o][128 px] = sum over 9 n: Whi*Xhi + Whi*Xlo + Wlo*Xhi (fp32 accum)
// 8 warps; warp tile 64 o x 32 px = 16 m16n8 fragments
__global__ void __launch_bounds__(256, 1) main_kernel(float* __restrict__ out) {
    extern __shared__ char S[];
    uint32_t sb = smem_u32(S);
    int tid  = threadIdx.x;
    int wid  = tid >> 5;
    int lane = tid & 31;
    int pt0  = blockIdx.x * PT;

    float4* sg   = (float4*)(S + SM_SG);
    int4*   sidx = (int4*)  (S + SM_SIDX);

    int o0  = (wid >> 2) * 64;
    int px0 = (wid & 3) * 32;

    // lane address components for ldmatrix (PTX fragment tables)
    int arow = (lane & 7) + ((lane >> 3) & 1) * 8;  // A: row within 16
    int akad = (lane >> 4) * 8;                     // A: k offset 0/8
    int brow = (lane & 7) + (lane >> 4) * 8;        // B: pixel row within 16
    int bkad = ((lane >> 3) & 1) * 8;               // B: k offset 0/8

    uint32_t aoff = sb + SM_WHI + (uint32_t)(o0 + arow)*XS + (uint32_t)akad*2;
    uint32_t boff = sb + SM_XHI + (uint32_t)(px0 + brow)*XS + (uint32_t)bkad*2;

    float d[16][4];
    #pragma unroll
    for (int t = 0; t < 16; t++)
        #pragma unroll
        for (int q = 0; q < 4; q++) d[t][q] = 0.f;

    const float4* xp4 = (const float4*)g_xp;

    for (int n = 0; n < 9; n++) {
        __syncthreads();   // previous iteration done reading smem
        if (tid < PT) {
            sg[tid]   = g_mg[(size_t)(pt0 + tid)*9 + n];
            sidx[tid] = g_midx[(size_t)(pt0 + tid)*9 + n];
        }
        // stage W hi/lo tiles (64KB) via cp.async: thread -> one 256B row
        {
            int th = tid >> 7;        // 0 = hi, 1 = lo
            int o  = tid & 127;
            const char* src = (const char*)g_wbf2 + (((size_t)n*2 + th)*128 + o)*256;
            uint32_t dst = sb + SM_WHI + th*TS + (uint32_t)o*XS;
            #pragma unroll
            for (int t = 0; t < 16; t++)
                cp16(dst + t*16, src + t*16);
            CP_COMMIT();
        }
        __syncthreads();   // sg/sidx visible

        // gather + bilinear blend + bf16 hi/lo split into X tiles
        {
            int px = tid >> 1;
            int hf = tid & 1;          // channel half (64 ch)
            float4 g = sg[px];
            int4  id = sidx[px];
            const float4* plt = xp4 + (size_t)id.x*32 + hf*16;
            const float4* prb = xp4 + (size_t)id.y*32 + hf*16;
            const float4* plb = xp4 + (size_t)id.z*32 + hf*16;
            const float4* prt = xp4 + (size_t)id.w*32 + hf*16;
            char* xh = S + SM_XHI + (size_t)px*XS + hf*128;
            #pragma unroll 4
            for (int q = 0; q < 16; q++) {
                float4 a = plt[q], r = prb[q], lb = plb[q], rt = prt[q];
                float4 v;
                v.x = g.x*a.x + g.y*r.x + g.z*lb.x + g.w*rt.x;
                v.y = g.x*a.y + g.y*r.y + g.z*lb.y + g.w*rt.y;
                v.z = g.x*a.z + g.y*r.z + g.z*lb.z + g.w*rt.z;
                v.w = g.x*a.w + g.y*r.w + g.z*lb.w + g.w*rt.w;
                uint32_t p01 = pack_bf16x2(v.y, v.x);
                uint32_t p23 = pack_bf16x2(v.w, v.z);
                uint32_t q01 = pack_bf16x2(v.y - bf16hi_f(p01), v.x - bf16lo_f(p01));
                uint32_t q23 = pack_bf16x2(v.w - bf16hi_f(p23), v.z - bf16lo_f(p23));
                *(uint32_t*)(xh + q*8)          = p01;
                *(uint32_t*)(xh + q*8 + 4)      = p23;
                *(uint32_t*)(xh + TS + q*8)     = q01;
                *(uint32_t*)(xh + TS + q*8 + 4) = q23;
            }
        }
        CP_WAIT0();
        __syncthreads();   // all tiles ready

        // MMA: 8 k-steps; per step: B(hi,lo) loads + per-mt A(hi) 8 mma + A(lo) 4 mma
        #pragma unroll 1
        for (int s = 0; s < 8; s++) {
            uint32_t ks = (uint32_t)s * 32;  // k0*2 bytes
            uint32_t bh[8], bl[8];
            ldsm4(boff + ks,                bh[0], bh[1], bh[2], bh[3]);
            ldsm4(boff + ks + 16*XS,        bh[4], bh[5], bh[6], bh[7]);
            ldsm4(boff + ks + TS,           bl[0], bl[1], bl[2], bl[3]);   // X lo tile
            ldsm4(boff + ks + TS + 16*XS,   bl[4], bl[5], bl[6], bl[7]);
            #pragma unroll
            for (int mt = 0; mt < 4; mt++) {
                uint32_t a[4];
                uint32_t ab = aoff + ks + (uint32_t)mt*16*XS;
                ldsm4(ab, a[0], a[1], a[2], a[3]);
                #pragma unroll
                for (int nt = 0; nt < 4; nt++) {
                    mma16816(d[mt*4 + nt], a, bh + nt*2);
                    mma16816(d[mt*4 + nt], a, bl + nt*2);
                }
                ldsm4(ab + TS, a[0], a[1], a[2], a[3]);   // W lo
                #pragma unroll
                for (int nt = 0; nt < 4; nt++)
                    mma16816(d[mt*4 + nt], a, bh + nt*2);
            }
        }
    }

    // epilogue: write NCHW output from fragments
    int b   = pt0 / HWIMG;
    int pim = pt0 % HWIMG;
    float* base = out + (size_t)b*OCH*HWIMG + pim;
    int g4 = lane >> 2, t4 = lane & 3;
    #pragma unroll
    for (int mt = 0; mt < 4; mt++) {
        #pragma unroll
        for (int nt = 0; nt < 4; nt++) {
            int o   = o0 + mt*16 + g4;
            int pxl = px0 + nt*8 + 2*t4;
            float* p0 = base + (size_t)o*HWIMG + pxl;
            *(float2*)p0 = make_float2(d[mt*4+nt][0], d[mt*4+nt][1]);
            *(float2*)(p0 + (size_t)8*HWIMG) = make_float2(d[mt*4+nt][2], d[mt*4+nt][3]);
        }
    }
}

// ---------------- launcher ---------------------------------------------------
extern "C" void kernel_launch(void* const* d_in, const int* in_sizes, int n_in,
                              void* d_out, int out_size) {
    const float* x        = (const float*)d_in[0];
    const float* conv_w   = (const float*)d_in[1];
    const float* pconv_w  = (const float*)d_in[2];
    const float* pconv_b  = (const float*)d_in[3];
    const float* adconv_w = (const float*)d_in[4];
    const float* adconv_b = (const float*)d_in[5];
    float* out = (float*)d_out;

    cudaFuncSetAttribute(main_kernel, cudaFuncAttributeMaxDynamicSharedMemorySize, SMEM_BYTES);

    prep_weights<<<288, 256>>>(conv_w, pconv_w, adconv_w);
    transpose_pad<<<dim3(12, 96, 2), dim3(32, 8)>>>(x);
    meta_kernel<<<NPIX/8, 256>>>(pconv_b, adconv_b);
    main_kernel<<<NBLK, 256, SMEM_BYTES>>>(out);
}

// round 10
// speedup vs baseline: 3.3280x; 1.5498x over previous
#include <cuda_runtime.h>
#include <math.h>
#include <stdint.h>

#define H 96
#define W 96
#define C 128
#define OCH 128
#define BATCH 2
#define HP 98
#define WP 98
#define HWIMG (H*W)              // 9216
#define NPIX (BATCH*H*W)         // 18432
#define PT 128                   // pixels per block
#define NBLK (NPIX/PT)           // 144

#define XS 272                   // smem row stride (256B data + 16B pad)
#define TS (128*XS)              // one 128x128 bf16 tile = 34816B

// dynamic smem: [Whi][Wlo][X0hi][X0lo][X1hi][X1lo]
#define SM_WHI 0
#define SM_X0  (2*TS)
#define SMEM_BYTES (6*TS)        // 208896

// ---------------- scratch (device globals; no allocation allowed) ----------
__device__ float    g_xp[BATCH*HP*WP*C];   // padded NHWC input (~9.8MB, borders 0)
__device__ uint32_t g_wbf2[9*2*128*64];    // [n][hi/lo][o][kpair] bf16x2 weights
__device__ float    g_wmeta[9*21*C];       // meta conv weights [n][f][c]
__device__ float4   g_mg[NPIX*9];          // bilinear weights (lt, rb, lb, rt)
__device__ int4     g_midx[NPIX*9];        // flat gather indices into xp (pixel units)

// ---------------- helpers ----------------------------------------------------
static __device__ __forceinline__ uint32_t smem_u32(const void* p) {
    uint32_t a;
    asm("{ .reg .u64 t; cvta.to.shared.u64 t, %1; cvt.u32.u64 %0, t; }" : "=r"(a) : "l"(p));
    return a;
}
static __device__ __forceinline__ void cp16(uint32_t dst_smem, const void* src) {
    asm volatile("cp.async.cg.shared.global [%0], [%1], 16;" :: "r"(dst_smem), "l"(src));
}
#define CP_COMMIT() asm volatile("cp.async.commit_group;")
#define CP_WAIT0()  asm volatile("cp.async.wait_group 0;")

static __device__ __forceinline__ uint32_t pack_bf16x2(float hi, float lo) {
    uint32_t r;
    asm("cvt.rn.bf16x2.f32 %0, %1, %2;" : "=r"(r) : "f"(hi), "f"(lo));
    return r;
}
static __device__ __forceinline__ float bf16hi_f(uint32_t p) { return __uint_as_float(p & 0xffff0000u); }
static __device__ __forceinline__ float bf16lo_f(uint32_t p) { return __uint_as_float(p << 16); }

static __device__ __forceinline__ void ldsm4(uint32_t a, uint32_t& r0, uint32_t& r1,
                                             uint32_t& r2, uint32_t& r3) {
    asm volatile("ldmatrix.sync.aligned.m8n8.x4.shared.b16 {%0,%1,%2,%3}, [%4];"
                 : "=r"(r0), "=r"(r1), "=r"(r2), "=r"(r3) : "r"(a));
}
static __device__ __forceinline__ void mma16816(float* d, const uint32_t* a,
                                                const uint32_t* b) {
    asm volatile("mma.sync.aligned.m16n8k16.row.col.f32.bf16.bf16.f32 "
                 "{%0,%1,%2,%3}, {%4,%5,%6,%7}, {%8,%9}, {%0,%1,%2,%3};"
                 : "+f"(d[0]), "+f"(d[1]), "+f"(d[2]), "+f"(d[3])
                 : "r"(a[0]), "r"(a[1]), "r"(a[2]), "r"(a[3]), "r"(b[0]), "r"(b[1]));
}

// blend 4 taps with bilinear weights, split bf16 hi/lo, store 8B to X row
static __device__ __forceinline__ void blend_sts(float4 t0, float4 t1, float4 t2, float4 t3,
                                                 float4 g, char* xrow, int lane) {
    float4 v;
    v.x = g.x*t0.x + g.y*t1.x + g.z*t2.x + g.w*t3.x;
    v.y = g.x*t0.y + g.y*t1.y + g.z*t2.y + g.w*t3.y;
    v.z = g.x*t0.z + g.y*t1.z + g.z*t2.z + g.w*t3.z;
    v.w = g.x*t0.w + g.y*t1.w + g.z*t2.w + g.w*t3.w;
    uint32_t p01 = pack_bf16x2(v.y, v.x);
    uint32_t p23 = pack_bf16x2(v.w, v.z);
    uint32_t q01 = pack_bf16x2(v.y - bf16hi_f(p01), v.x - bf16lo_f(p01));
    uint32_t q23 = pack_bf16x2(v.w - bf16hi_f(p23), v.z - bf16lo_f(p23));
    *(uint2*)(xrow + 8*lane)      = make_uint2(p01, p23);
    *(uint2*)(xrow + TS + 8*lane) = make_uint2(q01, q23);
}

// ---------------- weight prep ----------------------------------------------
__global__ void prep_weights(const float* __restrict__ conv_w,
                             const float* __restrict__ pconv_w,
                             const float* __restrict__ adconv_w) {
    int lin = blockIdx.x * blockDim.x + threadIdx.x;
    if (lin < 9*128*64) {                     // (n, o, kpair)
        int kp = lin & 63;
        int o  = (lin >> 6) & 127;
        int n  = lin >> 13;
        float w0 = conv_w[(o*C + 2*kp)*9 + n];
        float w1 = conv_w[(o*C + 2*kp + 1)*9 + n];
        uint32_t phi = pack_bf16x2(w1, w0);   // lo16 = even channel
        float l0 = w0 - bf16lo_f(phi);
        float l1 = w1 - bf16hi_f(phi);
        uint32_t plo = pack_bf16x2(l1, l0);
        g_wbf2[(((size_t)n*2 + 0)*128 + o)*64 + kp] = phi;
        g_wbf2[(((size_t)n*2 + 1)*128 + o)*64 + kp] = plo;
    }
    if (lin < 9*21*C) {
        int c = lin % C;
        int f = (lin / C) % 21;
        int n = lin / (21*C);
        g_wmeta[lin] = (f < 18) ? pconv_w[(f*C + c)*9 + n]
                                : adconv_w[((f-18)*C + c)*9 + n];
    }
}

// ---------------- NCHW -> padded NHWC transpose -----------------------------
__global__ void transpose_pad(const float* __restrict__ x) {
    __shared__ float tile[32][33];
    int b = blockIdx.z, i = blockIdx.y;
    int tj = blockIdx.x % 3;
    int tc = blockIdx.x / 3;
    int j0 = tj * 32, c0 = tc * 32;
    int tx = threadIdx.x, ty = threadIdx.y;   // 32 x 8

    const float* src = x + ((size_t)(b*C) * H + i) * W;
    #pragma unroll
    for (int q = 0; q < 4; q++) {
        int c = c0 + ty + q*8;
        tile[ty + q*8][tx] = src[(size_t)c * H * W + j0 + tx];
    }
    __syncthreads();
    float* dst = g_xp + (((size_t)b*HP) + (i+1)) * WP * C;
    #pragma unroll
    for (int q = 0; q < 4; q++) {
        int jj = j0 + ty + q*8;
        dst[(size_t)(jj+1)*C + c0 + tx] = tile[tx][ty + q*8];
    }
}

// ---------------- meta: 4 pixels per warp, smem reduction --------------------
__global__ void __launch_bounds__(256) meta_kernel(const float* __restrict__ pconv_b,
                                                   const float* __restrict__ adconv_b) {
    __shared__ float red[8][4][24];
    int gwarp = (blockIdx.x * blockDim.x + threadIdx.x) >> 5;
    int wib   = (threadIdx.x >> 5);
    int lane  = threadIdx.x & 31;
    if (gwarp >= NPIX/4) return;
    int pix0 = gwarp * 4;
    int b = pix0 / (H*W);
    int rem = pix0 % (H*W);
    int i = rem / W;
    int j0 = rem % W;          // multiple of 4, so all 4 px share row i

    float part[4][21];
    #pragma unroll
    for (int p = 0; p < 4; p++)
        #pragma unroll
        for (int f = 0; f < 21; f++) part[p][f] = 0.f;

    const float4* wm4 = (const float4*)g_wmeta;
    #pragma unroll
    for (int n = 0; n < 9; n++) {
        int kr = n / 3, kc = n % 3;
        float4 xv[4];
        #pragma unroll
        for (int p = 0; p < 4; p++)
            xv[p] = ((const float4*)(g_xp + (size_t)(((b*HP) + (i+kr))*WP + (j0+p+kc)) * C))[lane];
        const float4* wrow = wm4 + (size_t)(n*21)*32 + lane;
        #pragma unroll
        for (int f = 0; f < 21; f++) {
            float4 wv = wrow[(size_t)f*32];
            #pragma unroll
            for (int p = 0; p < 4; p++)
                part[p][f] += xv[p].x*wv.x + xv[p].y*wv.y + xv[p].z*wv.z + xv[p].w*wv.w;
        }
    }
    #pragma unroll
    for (int p = 0; p < 4; p++)
        #pragma unroll
        for (int f = 0; f < 21; f++) {
            float s = part[p][f];
            #pragma unroll
            for (int sh = 16; sh; sh >>= 1)
                s += __shfl_xor_sync(0xffffffffu, s, sh);
            if (lane == 0) red[wib][p][f] = s;
        }
    __syncwarp();

    #pragma unroll
    for (int p = 0; p < 4; p++) {
        if (lane < 9) {
            int n = lane;
            int j = j0 + p;
            int pix = pix0 + p;
            float offx = red[wib][p][n]     + pconv_b[n];
            float offy = red[wib][p][9 + n] + pconv_b[9 + n];
            int m = n % 3;
            float adv = red[wib][p][18 + m] + adconv_b[m];
            float adb = 1.f - 1.f / (1.f + expf(-adv));   // 1 - sigmoid
            float pnx = (float)(n / 3 - 1);
            float pny = (float)(n % 3 - 1);
            float px = (float)(i + 1) + pnx * (1.f + 2.f*adb) + offx;
            float py = (float)(j + 1) + pny * (1.f + 2.f*adb) + offy;

            float flx = floorf(px), fly = floorf(py);
            int qltx = min(max((int)flx,     0), HP-1);
            int qlty = min(max((int)fly,     0), WP-1);
            int qrbx = min(max((int)flx + 1, 0), HP-1);
            int qrby = min(max((int)fly + 1, 0), WP-1);
            bool mx = (px < 1.f) || (px > (float)(HP-2));
            bool my = (py < 1.f) || (py > (float)(WP-2));
            float pxe = mx ? fminf(fmaxf(flx, 0.f), (float)(HP-1)) : fminf(fmaxf(px, 0.f), (float)(HP-1));
            float pye = my ? fminf(fmaxf(fly, 0.f), (float)(WP-1)) : fminf(fmaxf(py, 0.f), (float)(WP-1));

            float glt_x = 1.f + ((float)qltx - pxe);
            float glt_y = 1.f + ((float)qlty - pye);
            float grb_x = 1.f - ((float)qrbx - pxe);
            float grb_y = 1.f - ((float)qrby - pye);

            float4 g = make_float4(glt_x*glt_y, grb_x*grb_y, glt_x*grb_y, grb_x*glt_y);
            int base = b * HP * WP;
            int4 idx = make_int4(base + qltx*WP + qlty,
                                 base + qrbx*WP + qrby,
                                 base + qltx*WP + qrby,
                                 base + qrbx*WP + qlty);
            g_mg[(size_t)pix*9 + n]   = g;
            g_midx[(size_t)pix*9 + n] = idx;
        }
    }
}

// ---------------- main: pipelined mma.sync bf16-split gather-GEMM -----------
// D[128 o][128 px] = sum over 9 n: Whi*Xhi + Whi*Xlo + Wlo*Xhi (fp32 accum)
// 8 warps, warp tile 64 o x 32 px; gather for n+1 interleaved with MMA of n
__global__ void __launch_bounds__(256, 1) main_kernel(float* __restrict__ out) {
    extern __shared__ char S[];
    uint32_t sb = smem_u32(S);
    int tid  = threadIdx.x;
    int wid  = tid >> 5;
    int lane = tid & 31;
    int pt0  = blockIdx.x * PT;

    int o0  = (wid >> 2) * 64;
    int px0 = (wid & 3) * 32;

    int arow = (lane & 7) + ((lane >> 3) & 1) * 8;
    int akad = (lane >> 4) * 8;
    int brow = (lane & 7) + (lane >> 4) * 8;
    int bkad = ((lane >> 3) & 1) * 8;

    uint32_t aoff = sb + SM_WHI + (uint32_t)(o0 + arow)*XS + (uint32_t)akad*2;
    uint32_t boff_base = sb + (uint32_t)(px0 + brow)*XS + (uint32_t)bkad*2;

    float d[16][4];
    #pragma unroll
    for (int t = 0; t < 16; t++)
        #pragma unroll
        for (int q = 0; q < 4; q++) d[t][q] = 0.f;

    const float4* xp4 = (const float4*)g_xp;

    // ---- prologue: stage W(0); gather X(0) into buf0 ----
    {
        int th = tid >> 7, o = tid & 127;
        const char* src = (const char*)g_wbf2 + (((size_t)0*2 + th)*128 + o)*256;
        uint32_t dst = sb + SM_WHI + th*TS + (uint32_t)o*XS;
        #pragma unroll
        for (int t = 0; t < 16; t++) cp16(dst + t*16, src + t*16);
        CP_COMMIT();
    }
    #pragma unroll 1
    for (int p = 0; p < 16; p++) {
        int px = wid*16 + p;
        size_t m = (size_t)(pt0 + px)*9 + 0;
        int4 id = g_midx[m];
        float4 g = g_mg[m];
        float4 t0 = xp4[(size_t)id.x*32 + lane];
        float4 t1 = xp4[(size_t)id.y*32 + lane];
        float4 t2 = xp4[(size_t)id.z*32 + lane];
        float4 t3 = xp4[(size_t)id.w*32 + lane];
        blend_sts(t0, t1, t2, t3, g, S + SM_X0 + (size_t)px*XS, lane);
    }

    // ---- main loop over 9 taps ----
    for (int n = 0; n < 9; n++) {
        CP_WAIT0();        // W(n) landed (own group)
        __syncthreads();   // W(n) + X(n) visible block-wide
        uint32_t xcons = SM_X0 + (uint32_t)(n & 1) * (2*TS);
        uint32_t xprod = SM_X0 + (uint32_t)((n + 1) & 1) * (2*TS);
        uint32_t boff  = boff_base + xcons;
        bool pf = (n < 8);

        int4 ida, idb, nida, nidb;
        float4 ga, gb, nga, ngb;
        if (pf) {
            size_t m = (size_t)(pt0 + wid*16)*9 + (n + 1);
            ida = g_midx[m];     ga = g_mg[m];
            idb = g_midx[m + 9]; gb = g_mg[m + 9];
        }

        #pragma unroll 1
        for (int s = 0; s < 8; s++) {
            // prefetch taps for pixel pair (2s, 2s+1) of n+1
            float4 T0, T1, T2, T3, U0, U1, U2, U3;
            if (pf) {
                T0 = xp4[(size_t)ida.x*32 + lane];
                T1 = xp4[(size_t)ida.y*32 + lane];
                T2 = xp4[(size_t)ida.z*32 + lane];
                T3 = xp4[(size_t)ida.w*32 + lane];
                U0 = xp4[(size_t)idb.x*32 + lane];
                U1 = xp4[(size_t)idb.y*32 + lane];
                U2 = xp4[(size_t)idb.z*32 + lane];
                U3 = xp4[(size_t)idb.w*32 + lane];
                if (s < 7) {    // rotate meta for next pair
                    size_t m = (size_t)(pt0 + wid*16 + 2*(s+1))*9 + (n + 1);
                    nida = g_midx[m];     nga = g_mg[m];
                    nidb = g_midx[m + 9]; ngb = g_mg[m + 9];
                }
            }

            // MMA step s (K slice 16)
            uint32_t ks = (uint32_t)s * 32;
            uint32_t bh[8], bl[8];
            ldsm4(boff + ks,              bh[0], bh[1], bh[2], bh[3]);
            ldsm4(boff + ks + 16*XS,      bh[4], bh[5], bh[6], bh[7]);
            ldsm4(boff + ks + TS,         bl[0], bl[1], bl[2], bl[3]);
            ldsm4(boff + ks + TS + 16*XS, bl[4], bl[5], bl[6], bl[7]);
            #pragma unroll
            for (int mt = 0; mt < 4; mt++) {
                uint32_t a[4];
                uint32_t ab = aoff + ks + (uint32_t)mt*16*XS;
                ldsm4(ab, a[0], a[1], a[2], a[3]);
                #pragma unroll
                for (int nt = 0; nt < 4; nt++) {
                    mma16816(d[mt*4 + nt], a, bh + nt*2);
                    mma16816(d[mt*4 + nt], a, bl + nt*2);
                }
                ldsm4(ab + TS, a[0], a[1], a[2], a[3]);   // W lo
                #pragma unroll
                for (int nt = 0; nt < 4; nt++)
                    mma16816(d[mt*4 + nt], a, bh + nt*2);
            }

            // blend + store pixel pair into produce buffer
            if (pf) {
                char* xr = S + xprod + (size_t)(wid*16 + 2*s)*XS;
                blend_sts(T0, T1, T2, T3, ga, xr, lane);
                blend_sts(U0, U1, U2, U3, gb, xr + XS, lane);
                ida = nida; ga = nga;
                idb = nidb; gb = ngb;
            }
        }

        __syncthreads();   // MMA(n) done with W before restage; STS(n+1) done
        if (pf) {          // stage W(n+1)
            int th = tid >> 7, o = tid & 127;
            const char* src = (const char*)g_wbf2 + (((size_t)(n+1)*2 + th)*128 + o)*256;
            uint32_t dst = sb + SM_WHI + th*TS + (uint32_t)o*XS;
            #pragma unroll
            for (int t = 0; t < 16; t++) cp16(dst + t*16, src + t*16);
            CP_COMMIT();
        }
    }

    // ---- epilogue: write NCHW output from fragments ----
    int b   = pt0 / HWIMG;
    int pim = pt0 % HWIMG;
    float* base = out + (size_t)b*OCH*HWIMG + pim;
    int g4 = lane >> 2, t4 = lane & 3;
    #pragma unroll
    for (int mt = 0; mt < 4; mt++) {
        #pragma unroll
        for (int nt = 0; nt < 4; nt++) {
            int o   = o0 + mt*16 + g4;
            int pxl = px0 + nt*8 + 2*t4;
            float* p0 = base + (size_t)o*HWIMG + pxl;
            *(float2*)p0 = make_float2(d[mt*4+nt][0], d[mt*4+nt][1]);
            *(float2*)(p0 + (size_t)8*HWIMG) = make_float2(d[mt*4+nt][2], d[mt*4+nt][3]);
        }
    }
}

// ---------------- launcher ---------------------------------------------------
extern "C" void kernel_launch(void* const* d_in, const int* in_sizes, int n_in,
                              void* d_out, int out_size) {
    const float* x        = (const float*)d_in[0];
    const float* conv_w   = (const float*)d_in[1];
    const float* pconv_w  = (const float*)d_in[2];
    const float* pconv_b  = (const float*)d_in[3];
    const float* adconv_w = (const float*)d_in[4];
    const float* adconv_b = (const float*)d_in[5];
    float* out = (float*)d_out;

    cudaFuncSetAttribute(main_kernel, cudaFuncAttributeMaxDynamicSharedMemorySize, SMEM_BYTES);

    prep_weights<<<288, 256>>>(conv_w, pconv_w, adconv_w);
    transpose_pad<<<dim3(12, 96, 2), dim3(32, 8)>>>(x);
    meta_kernel<<<(NPIX/4)/8, 256>>>(pconv_b, adconv_b);
    main_kernel<<<NBLK, 256, SMEM_BYTES>>>(out);
}